// round 7
// baseline (speedup 1.0000x reference)
#include <cuda_runtime.h>
#include <cuda_fp16.h>
#include <math.h>
#include <stdint.h>

// GMM_64003602645506 — warp-independent fp16 mma.sync GEMM, barrier-free.
// R7: 24 warps/CTA (6/SMSP), m16xn64 per warp, 16-sample steal units;
// prep_kernel local-memory spill fixed (solve via smem).

#define D        32
#define K        64
#define NG       84
#define NKS      42
#define UNIT     16
#define TPB      768
#define NWARP    24
#define LOG_2PI  1.8378770664093453f

// smem layout (bytes)
#define SB_WORDS  (NKS * 4 * 32 * 4)          // 21504 uint32 (86016 B)
#define SB_OFF    0
#define XBUF_W    (UNIT * 20)                 // 320 uint32 per warp per parity
#define XE_OFF    86016
#define XO_OFF    (XE_OFF + NWARP * XBUF_W * 4)   // +30720
#define SLC_OFF   (XO_OFF + NWARP * XBUF_W * 4)   // +30720
#define SLW_OFF   (SLC_OFF + 256)
#define SGRP_OFF  (SLW_OFF + 256)
#define SMEM_TOTAL (SGRP_OFF + 512)

__device__ uint32_t g_Bfrag[SB_WORDS];
__device__ float  g_lc[K];
__device__ float  g_lwv[K];
__device__ double g_acc;
__device__ int    g_counter;
__device__ int    g_done;

__device__ __forceinline__ void gdecode(int g, int& e, int& d, bool& lin) {
    if (g >= 80) { lin = true; e = (g - 80) * 8; d = 0; return; }
    lin = false;
    if (g < 32)      { d = g >> 2;            e = (g & 3) * 8; }
    else if (g < 56) { d = 8 + (g - 32) / 3;  e = ((g - 32) % 3) * 8; }
    else if (g < 72) { d = 16 + ((g - 56) >> 1); e = ((g - 56) & 1) * 8; }
    else             { d = 24 + (g - 72);     e = 0; }
}

__device__ __forceinline__ uint32_t hmul2u(uint32_t a, uint32_t b) {
    __half2 r = __hmul2(*(__half2*)&a, *(__half2*)&b);
    return *(uint32_t*)&r;
}

__device__ __forceinline__ void mmaf16(float* c, uint32_t a0, uint32_t a1,
                                       uint32_t a2, uint32_t a3,
                                       uint32_t b0, uint32_t b1) {
    asm volatile(
        "mma.sync.aligned.m16n8k16.row.col.f32.f16.f16.f32 "
        "{%0,%1,%2,%3}, {%4,%5,%6,%7}, {%8,%9}, {%0,%1,%2,%3};"
        : "+f"(c[0]), "+f"(c[1]), "+f"(c[2]), "+f"(c[3])
        : "r"(a0), "r"(a1), "r"(a2), "r"(a3), "r"(b0), "r"(b1));
}

// ---------------------------------------------------------------------------
// Prep: 64 blocks x 32 threads. Local-array spill removed: forward
// substitution writes progressively into smem As (same-thread RAW only).
// ---------------------------------------------------------------------------
__global__ void prep_kernel(const float* __restrict__ means,
                            const float* __restrict__ scale_tril,
                            const float* __restrict__ log_weights) {
    int k = blockIdx.x, t = threadIdx.x;
    __shared__ float Ls[D][D], As[D][D + 1], mu[D], u[D], b[D];

    for (int i = t; i < D * D; i += 32)
        Ls[i / D][i % D] = scale_tril[k * D * D + i];
    mu[t] = means[k * D + t];
    __syncwarp();

    float hld = logf(Ls[t][t]);
    #pragma unroll
    for (int o = 16; o; o >>= 1) hld += __shfl_xor_sync(~0u, hld, o);

    // A = L^-1, column t, progressive smem writes (no local array)
    {
        #pragma unroll
        for (int i = 0; i < D; i++) As[i][t] = 0.0f;
        As[t][t] = 1.0f / Ls[t][t];
        for (int i = t + 1; i < D; i++) {
            float s = 0.0f;
            for (int j = t; j < i; j++) s = fmaf(Ls[i][j], As[j][t], s);
            As[i][t] = -s / Ls[i][i];
        }
    }
    __syncwarp();

    { float s = 0.0f; for (int j = 0; j <= t; j++) s += As[t][j] * mu[j]; u[t] = s; }
    __syncwarp();
    { float s = 0.0f; for (int r = t; r < D; r++) s += As[r][t] * u[r]; b[t] = s; }
    __syncwarp();
    float c = b[t] * mu[t];
    #pragma unroll
    for (int o = 16; o; o >>= 1) c += __shfl_xor_sync(~0u, c, o);

    float v0 = log_weights[t], v1 = log_weights[t + 32];
    float mx = fmaxf(v0, v1);
    #pragma unroll
    for (int o = 16; o; o >>= 1) mx = fmaxf(mx, __shfl_xor_sync(~0u, mx, o));
    float se = expf(v0 - mx) + expf(v1 - mx);
    #pragma unroll
    for (int o = 16; o; o >>= 1) se += __shfl_xor_sync(~0u, se, o);
    float lse = mx + logf(se);

    __half* Bh = (__half*)g_Bfrag;
    for (int idx = t; idx < NG * 8; idx += 32) {
        int g = idx >> 3, cc = idx & 7;
        int e, d; bool lin;
        gdecode(g, e, d, lin);
        float v;
        if (lin) {
            v = -2.0f * b[e + cc];
        } else {
            int i = e + cc, j = i + d;
            if (j > 31) v = 0.0f;
            else {
                float s = 0.0f;
                for (int r = j; r < D; r++) s += As[r][i] * As[r][j];
                v = (d == 0) ? s : 2.0f * s;
            }
        }
        int kk = (g & 1) * 8 + cc, s_ = g >> 1;
        int rr = kk >> 3, kkl = kk & 7, tt = kkl >> 1, hh = kkl & 1;
        int nt = k >> 3, q = nt >> 1, w = (nt & 1) * 2 + rr;
        int L = (k & 7) * 4 + tt;
        Bh[((((s_ * 4 + q) * 32 + L) * 4) + w) * 2 + hh] = __float2half(v);
    }

    if (t == 0) {
        float lwk = log_weights[k] - lse;
        g_lwv[k] = lwk;
        g_lc[k]  = -0.5f * (c + (float)D * LOG_2PI) - hld + lwk;
        if (k == 0) { g_acc = 0.0; g_counter = 0; g_done = 0; }
    }
}

// ---------------------------------------------------------------------------
// Main: persistent, 24 independent warps per CTA, each m16 x n64 per unit.
// ---------------------------------------------------------------------------
__global__ void __launch_bounds__(TPB, 1) gmm_main(const float* __restrict__ X,
                                                   float* __restrict__ out,
                                                   int N, int nunits) {
    extern __shared__ char smem[];
    const int tid = threadIdx.x;
    const int wid = tid >> 5;
    const int lane = tid & 31;
    const int gq = lane >> 2;                 // row group 0..7
    const int t  = lane & 3;

    float* sLC = (float*)(smem + SLC_OFF);
    float* sLW = (float*)(smem + SLW_OFF);
    uint32_t* sGrp = (uint32_t*)(smem + SGRP_OFF);
    const uint4* sB4 = (const uint4*)(smem + SB_OFF);

    for (int i = tid; i < SB_WORDS; i += TPB)
        ((uint32_t*)(smem + SB_OFF))[i] = g_Bfrag[i];
    if (tid < K) { sLC[tid] = g_lc[tid]; sLW[tid] = g_lwv[tid]; }
    if (tid < NG) {
        int e, d; bool lin;
        gdecode(tid, e, d, lin);
        int j2 = e + d;
        sGrp[tid] = (uint32_t)(e >> 1) | ((uint32_t)(j2 >> 1) << 8)
                  | ((uint32_t)(j2 & 1) << 16) | (lin ? (1u << 17) : 0u);
    }
    __syncthreads();

    uint32_t* xe = (uint32_t*)(smem + XE_OFF) + wid * XBUF_W;
    uint32_t* xo = (uint32_t*)(smem + XO_OFF) + wid * XBUF_W;

    // rows gq, gq+8; addr = row*20 + t
    const int rb0 = gq * 20 + t;
    const int rb1 = (gq + 8) * 20 + t;

    float accf = 0.0f;

    for (;;) {
        int u;
        if (lane == 0) u = atomicAdd(&g_counter, 1);
        u = __shfl_sync(~0u, u, 0);
        if (u >= nunits) break;
        const int base = u * UNIT;

        __syncwarp();
        // stage x: lanes 0..15 handle row = lane
        if (lane < UNIT) {
            int row = lane;
            int n = base + row;
            float xv[33];
            if (n < N) {
                const float4* xp = (const float4*)X + (size_t)n * 8;
                #pragma unroll
                for (int v = 0; v < 8; v++) {
                    float4 f4 = xp[v];
                    xv[4*v] = f4.x; xv[4*v+1] = f4.y;
                    xv[4*v+2] = f4.z; xv[4*v+3] = f4.w;
                }
            } else {
                #pragma unroll
                for (int i = 0; i < D; i++) xv[i] = 0.0f;
            }
            xv[32] = 0.0f;
            uint32_t* xer = xe + row * 20;
            uint32_t* xor_ = xo + row * 20;
            #pragma unroll
            for (int p = 0; p < 16; p++) {
                __half2 h = __floats2half2_rn(xv[2*p], xv[2*p+1]);
                xer[p] = *(uint32_t*)&h;
                __half2 ho = __floats2half2_rn(xv[2*p+1], xv[2*p+2]);
                xor_[p] = *(uint32_t*)&ho;
            }
            #pragma unroll
            for (int p = 16; p < 20; p++) { xer[p] = 0u; xor_[p] = 0u; }
        }
        __syncwarp();

        float acc[8][4];
        #pragma unroll
        for (int nt = 0; nt < 8; nt++)
            #pragma unroll
            for (int r = 0; r < 4; r++) acc[nt][r] = 0.0f;

        for (int s = 0; s < NKS; s++) {
            uint32_t gE = sGrp[2 * s], gO = sGrp[2 * s + 1];
            int p1E = gE & 0xff, p2E = (gE >> 8) & 0xff;
            int p1O = gO & 0xff, p2O = (gO >> 8) & 0xff;
            const uint32_t* x2E = ((gE >> 16) & 1) ? xo : xe;
            const uint32_t* x2O = ((gO >> 16) & 1) ? xo : xe;
            const bool linE = (gE >> 17) & 1, linO = (gO >> 17) & 1;

            uint32_t e1, e2, a0, a1, a2, a3;
            e1 = xe[rb0 + p1E]; e2 = x2E[rb0 + p2E];
            a0 = linE ? e1 : hmul2u(e1, e2);
            e1 = xe[rb1 + p1E]; e2 = x2E[rb1 + p2E];
            a1 = linE ? e1 : hmul2u(e1, e2);
            e1 = xe[rb0 + p1O]; e2 = x2O[rb0 + p2O];
            a2 = linO ? e1 : hmul2u(e1, e2);
            e1 = xe[rb1 + p1O]; e2 = x2O[rb1 + p2O];
            a3 = linO ? e1 : hmul2u(e1, e2);

            #pragma unroll
            for (int q = 0; q < 4; q++) {
                uint4 B = sB4[(s * 4 + q) * 32 + lane];
                mmaf16(acc[2*q],   a0, a1, a2, a3, B.x, B.y);
                mmaf16(acc[2*q+1], a0, a1, a2, a3, B.z, B.w);
            }
        }

        // epilogue: rows gq, gq+8; constants read from smem (reg pressure)
        #pragma unroll
        for (int rh = 0; rh < 2; rh++) {
            int n = base + gq + 8 * rh;
            float glp[16], mx = -1e30f;
            #pragma unroll
            for (int nt = 0; nt < 8; nt++) {
                #pragma unroll
                for (int h = 0; h < 2; h++) {
                    int col = nt * 8 + 2 * t + h;
                    float g = fmaf(-0.5f, acc[nt][rh * 2 + h], sLC[col]);
                    glp[nt * 2 + h] = g;
                    mx = fmaxf(mx, g);
                }
            }
            mx = fmaxf(mx, __shfl_xor_sync(~0u, mx, 1));
            mx = fmaxf(mx, __shfl_xor_sync(~0u, mx, 2));
            float S = 0.0f, T = 0.0f;
            #pragma unroll
            for (int nt = 0; nt < 8; nt++) {
                #pragma unroll
                for (int h = 0; h < 2; h++) {
                    int col = nt * 8 + 2 * t + h;
                    float e = __expf(glp[nt * 2 + h] - mx);
                    S += e;
                    T = fmaf(e, glp[nt * 2 + h] - sLW[col], T);
                }
            }
            S += __shfl_xor_sync(~0u, S, 1);
            S += __shfl_xor_sync(~0u, S, 2);
            T += __shfl_xor_sync(~0u, T, 1);
            T += __shfl_xor_sync(~0u, T, 2);
            if (t == 0 && n < N) accf += T / S;
        }
    }

    #pragma unroll
    for (int o = 16; o; o >>= 1) accf += __shfl_xor_sync(~0u, accf, o);
    if (lane == 0) atomicAdd(&g_acc, (double)accf);

    __syncthreads();
    __threadfence();
    if (tid == 0) {
        if (atomicAdd(&g_done, 1) == (int)gridDim.x - 1) {
            double total = atomicAdd(&g_acc, 0.0);
            out[0] = (float)(-total / (double)N);
        }
    }
}

// ---------------------------------------------------------------------------
extern "C" void kernel_launch(void* const* d_in, const int* in_sizes, int n_in,
                              void* d_out, int out_size) {
    const float* X           = (const float*)d_in[0];
    const float* means       = (const float*)d_in[1];
    const float* scale_tril  = (const float*)d_in[2];
    const float* log_weights = (const float*)d_in[3];
    float* out = (float*)d_out;

    int N = in_sizes[0] / D;
    int nunits = (N + UNIT - 1) / UNIT;

    cudaFuncSetAttribute(gmm_main, cudaFuncAttributeMaxDynamicSharedMemorySize,
                         SMEM_TOTAL);
    int nsm = 148;
    cudaDeviceGetAttribute(&nsm, cudaDevAttrMultiProcessorCount, 0);

    prep_kernel<<<K, 32>>>(means, scale_tril, log_weights);
    gmm_main<<<nsm, TPB, SMEM_TOTAL>>>(X, out, N, nunits);
}